// round 16
// baseline (speedup 1.0000x reference)
#include <cuda_runtime.h>
#include <cuda_bf16.h>
#include <cstdint>

// AllZeroDigitalFilter: time-varying FIR, y = A0 + w*(A1-A0).
// R14: R12 structure (4 samples/thread, 160 thr, 640-sample tiles, packed
// (A0,A1) f32x2 accumulators) but x tile stored PRE-DUPLICATED in smem:
// xd[i] = (x[i], x[i]).  One LDS.128 = two ready (x,x) FFMA2 operands in
// aligned pairs -> zero splat MOVs in the inner loop.

#define TAPS         50
#define TAPS_PAD     52
#define NGROUPS      (TAPS_PAD / 4)          // 13
#define FRAME_P      80
#define FRAMES_PER_BLOCK 8
#define SAMP_PER_BLOCK   (FRAMES_PER_BLOCK * FRAME_P)   // 640
#define SAMP_PER_THREAD  4
#define THREADS_PER_BLOCK (SAMP_PER_BLOCK / SAMP_PER_THREAD) // 160
#define XPAD         56                      // mult of 8, >= 51+3
#define X_TILE       (SAMP_PER_BLOCK + XPAD + 8)        // 704

typedef unsigned long long u64;
typedef unsigned int u32;

__device__ __forceinline__ void fma2(u64& acc, u64 a, u64 b) {
    asm("fma.rn.f32x2 %0, %1, %2, %0;" : "+l"(acc) : "l"(a), "l"(b));
}
__device__ __forceinline__ void unpack2(float& lo, float& hi, u64 v) {
    asm("mov.b64 {%0, %1}, %2;" : "=f"(lo), "=f"(hi) : "l"(v));
}

__global__ __launch_bounds__(THREADS_PER_BLOCK)
void azdf_kernel(const float* __restrict__ x,
                 const float* __restrict__ bcoef,
                 float* __restrict__ y,
                 int T, int N)
{
    // duplicated x tile: xd[i] = (x[t0-XPAD+i], same)
    __shared__ __align__(16) float2 xd[X_TILE];
    // bpair[r][k] = (b[n0+r][k], b[n0+r+1][k]); row = 52*8 = 416 B
    __shared__ __align__(16) float2 bpair[FRAMES_PER_BLOCK][TAPS_PAD];

    const int bidx = blockIdx.y;
    const int t0   = blockIdx.x * SAMP_PER_BLOCK;
    const int n0   = blockIdx.x * FRAMES_PER_BLOCK;
    const int tid  = threadIdx.x;

    const float* xg = x + (size_t)bidx * T;
    const float* bg = bcoef + (size_t)bidx * N * TAPS;

    // ---- stage duplicated x tile ----
    if (t0 >= XPAD && t0 + (X_TILE - XPAD) <= T) {
        const float4* src = reinterpret_cast<const float4*>(xg + t0 - XPAD);
        #pragma unroll
        for (int i = tid; i < X_TILE / 4; i += THREADS_PER_BLOCK) {
            float4 v = src[i];
            float2* d = &xd[4 * i];
            d[0] = make_float2(v.x, v.x);
            d[1] = make_float2(v.y, v.y);
            d[2] = make_float2(v.z, v.z);
            d[3] = make_float2(v.w, v.w);
        }
    } else {
        #pragma unroll
        for (int i = tid; i < X_TILE; i += THREADS_PER_BLOCK) {
            int g = t0 - XPAD + i;
            float v = (g >= 0 && g < T) ? xg[g] : 0.0f;
            xd[i] = make_float2(v, v);
        }
    }
    // ---- stage interleaved coeff pairs ----
    #pragma unroll
    for (int i = tid; i < FRAMES_PER_BLOCK * TAPS_PAD; i += THREADS_PER_BLOCK) {
        int r = i / TAPS_PAD;
        int k = i - r * TAPS_PAD;
        int n  = n0 + r;     if (n  > N - 1) n  = N - 1;
        int n1 = n0 + r + 1; if (n1 > N - 1) n1 = N - 1;
        float2 p;
        if (k < TAPS) {
            p.x = bg[(size_t)n  * TAPS + k];
            p.y = bg[(size_t)n1 * TAPS + k];
        } else {
            p.x = 0.0f; p.y = 0.0f;
        }
        bpair[r][k] = p;
    }
    __syncthreads();

    const int ls = tid * SAMP_PER_THREAD;   // local sample base (mult of 4)
    const int fr = ls / FRAME_P;            // frame in block
    const int p  = ls - fr * FRAME_P;       // phase (mult of 4)

    const ulonglong2* xd2 = reinterpret_cast<const ulonglong2*>(xd);
    const ulonglong2* cp2 = reinterpret_cast<const ulonglong2*>(bpair[fr]);

    u64 A[SAMP_PER_THREAD] = {0ull, 0ull, 0ull, 0ull};   // (A0,A1) per sample

    // Window: v[m] = dup(xs[XPAD+ls-4g-4+m]), m=0..7. Group g (taps k=4g+j)
    // uses v[4+s-j] (indices 1..7). Shift v[4..7]=v[0..3] (renamed), refill
    // v[0..3] with TWO LDS.128 from the dup array (each = 2 packed operands).
    const int dbase = (XPAD + ls) / 2;      // xd2 index of dup pair (ls, ls+1)
    u64 v[8];
    {
        ulonglong2 d0 = xd2[dbase - 2];     // dup[ls-4], dup[ls-3]
        ulonglong2 d1 = xd2[dbase - 1];     // dup[ls-2], dup[ls-1]
        ulonglong2 d2 = xd2[dbase];         // dup[ls+0], dup[ls+1]
        ulonglong2 d3 = xd2[dbase + 1];     // dup[ls+2], dup[ls+3]
        v[0] = d0.x; v[1] = d0.y; v[2] = d1.x; v[3] = d1.y;
        v[4] = d2.x; v[5] = d2.y; v[6] = d3.x; v[7] = d3.y;
    }

    #pragma unroll
    for (int g = 0; g < NGROUPS; ++g) {
        ulonglong2 cA = cp2[2 * g];          // coeff pairs taps 4g, 4g+1
        ulonglong2 cB = cp2[2 * g + 1];      // taps 4g+2, 4g+3
        const u64 c[4] = {cA.x, cA.y, cB.x, cB.y};

        #pragma unroll
        for (int j = 0; j < 4; ++j) {
            #pragma unroll
            for (int s = 0; s < SAMP_PER_THREAD; ++s)
                fma2(A[s], v[4 + s - j], c[j]);   // index 1..7
        }

        if (g < NGROUPS - 1) {
            // shift up by 4 (register renaming under full unroll)
            v[7] = v[3]; v[6] = v[2]; v[5] = v[1]; v[4] = v[0];
            ulonglong2 d0 = xd2[dbase - 2 * g - 4];
            ulonglong2 d1 = xd2[dbase - 2 * g - 3];
            v[0] = d0.x; v[1] = d0.y; v[2] = d1.x; v[3] = d1.y;
        }
    }

    // ---- blend and store ----
    float a0[SAMP_PER_THREAD], a1[SAMP_PER_THREAD];
    #pragma unroll
    for (int s = 0; s < SAMP_PER_THREAD; ++s) unpack2(a0[s], a1[s], A[s]);

    const int tglob = t0 + ls;
    const float invP = 1.0f / (float)FRAME_P;
    if (tglob + SAMP_PER_THREAD <= T) {
        float4 r;
        r.x = fmaf((float)(p + 0) * invP, a1[0] - a0[0], a0[0]);
        r.y = fmaf((float)(p + 1) * invP, a1[1] - a0[1], a0[1]);
        r.z = fmaf((float)(p + 2) * invP, a1[2] - a0[2], a0[2]);
        r.w = fmaf((float)(p + 3) * invP, a1[3] - a0[3], a0[3]);
        *reinterpret_cast<float4*>(y + (size_t)bidx * T + tglob) = r;
    } else {
        #pragma unroll
        for (int s = 0; s < SAMP_PER_THREAD; ++s) {
            int t = tglob + s;
            if (t < T) {
                float ww = (float)(p + s) * invP;
                y[(size_t)bidx * T + t] = fmaf(ww, a1[s] - a0[s], a0[s]);
            }
        }
    }
}

extern "C" void kernel_launch(void* const* d_in, const int* in_sizes, int n_in,
                              void* d_out, int out_size)
{
    const float* x = (const float*)d_in[0];   // (B, T) float32
    const float* b = (const float*)d_in[1];   // (B, N, 50) float32
    float* y = (float*)d_out;                 // (B, T) float32

    const int B = 8;
    const int T = in_sizes[0] / B;
    const int N = in_sizes[1] / (B * TAPS);

    dim3 grid((T + SAMP_PER_BLOCK - 1) / SAMP_PER_BLOCK, B);
    azdf_kernel<<<grid, THREADS_PER_BLOCK>>>(x, b, y, T, N);
}